// round 17
// baseline (speedup 1.0000x reference)
#include <cuda_runtime.h>
#include <cstdint>

// Problem constants
#define KS    5
#define NTAP  25
#define OH    508
#define OW    508
#define IH    512
#define IW    512
#define CI    3
#define BATCH 8
#define PLANE (OH * OW)              // 258064
#define WTOT  (BATCH * CI * PLANE)   // 6193536

// Band decomposition: each work item = TH full-width output rows of one batch
#define TH     2
#define NBAND  (OH / TH)             // 254
#define NWORK  (NBAND * BATCH)       // 2032
#define NCOMP  256                   // compute threads
#define NTHR   288                   // + 1 producer warp
#define NF4    (TH * (OW / 4))       // 254 float4 outputs per band
#define GRIDX  296                   // 148 SMs x 2 CTAs, uniform occupancy

// Staging: groups of 2 kernel-rows per ring slot (last group of band = 1 row)
#define TAPB   (TH * OW * 4)              // 4064 B per tap
#define ROWB   (KS * TAPB)                // 20320 B per kernel-row
#define SLOTB  (2 * ROWB)                 // 40640 B per slot (2 rows)
#define GPB    3                          // groups per band: rows {0,1},{2,3},{4}
#define RING   2
#define MBAR_OFF    (RING * SLOTB)        // 81280 (16B aligned)
#define SMEM_BYTES  (MBAR_OFF + 64)       // 81344

// ---- PTX helpers ----
__device__ __forceinline__ void mbar_init(uint32_t a, uint32_t cnt) {
    asm volatile("mbarrier.init.shared.b64 [%0], %1;" :: "r"(a), "r"(cnt) : "memory");
}
__device__ __forceinline__ void mbar_expect_tx(uint32_t a, uint32_t bytes) {
    asm volatile("mbarrier.arrive.expect_tx.shared.b64 _, [%0], %1;"
                 :: "r"(a), "r"(bytes) : "memory");
}
__device__ __forceinline__ void mbar_arrive(uint32_t a) {
    asm volatile("mbarrier.arrive.shared.b64 _, [%0];" :: "r"(a) : "memory");
}
__device__ __forceinline__ void mbar_wait(uint32_t a, uint32_t parity) {
    asm volatile(
        "{\n\t.reg .pred P1;\n\t"
        "WAIT_%=:\n\t"
        "mbarrier.try_wait.parity.acquire.cta.shared::cta.b64 P1, [%0], %1, 0x989680;\n\t"
        "@P1 bra.uni DONE_%=;\n\t"
        "bra.uni WAIT_%=;\n\t"
        "DONE_%=:\n\t}"
        :: "r"(a), "r"(parity) : "memory");
}
__device__ __forceinline__ uint64_t policy_evict_first() {
    uint64_t p;
    asm volatile("createpolicy.fractional.L2::evict_first.b64 %0, 1.0;" : "=l"(p));
    return p;
}
__device__ __forceinline__ void bulk_g2s_ef(uint32_t dst, const void* src,
                                            uint32_t bytes, uint32_t mbar,
                                            uint64_t pol) {
    asm volatile(
        "cp.async.bulk.shared::cluster.global.mbarrier::complete_tx::bytes"
        ".L2::cache_hint [%0], [%1], %2, [%3], %4;"
        :: "r"(dst), "l"(src), "r"(bytes), "r"(mbar), "l"(pol) : "memory");
}
__device__ __forceinline__ void stcs4(float* p, float4 v) {
    asm volatile("st.global.cs.v4.f32 [%0], {%1,%2,%3,%4};"
                 :: "l"(p), "f"(v.x), "f"(v.y), "f"(v.z), "f"(v.w));
}

// stage group s (global stage counter) into ring slot s%RING
__device__ __forceinline__ void stage_group(const float* __restrict__ kern,
                                            uint32_t sbase, uint32_t mb_full0,
                                            int bid, int s, uint64_t pol) {
    const int q   = s / GPB;            // CTA-local band index
    const int sg  = s % GPB;            // group within band
    const int di0 = sg * 2;
    const int nr  = (sg < 2) ? 2 : 1;   // rows in this group
    const int w   = bid + q * GRIDX;    // global work id (< NWORK guaranteed)
    const int band = w % NBAND;
    const int b    = w / NBAND;
    const int slot = s % RING;
    const uint32_t mb = mb_full0 + 8u * slot;
    mbar_expect_tx(mb, (uint32_t)(nr * ROWB));
    for (int rr = 0; rr < nr; ++rr) {
        const int di = di0 + rr;
        const float* src = kern + ((size_t)b * NTAP + di * KS) * PLANE
                                + (size_t)band * TH * OW;
        #pragma unroll
        for (int t = 0; t < KS; ++t)
            bulk_g2s_ef(sbase + (uint32_t)(slot * SLOTB + rr * ROWB + t * TAPB),
                        src + (size_t)t * PLANE, TAPB, mb, pol);
    }
}

// load 8 tensor floats per channel for (batch b, tensor row trow, col j)
__device__ __forceinline__ void loadT(float (&rT)[CI][8],
                                      const float* __restrict__ tens,
                                      int b, int trow, int j) {
    #pragma unroll
    for (int c = 0; c < CI; ++c) {
        const float* tp = tens + (((size_t)b * CI + c) * IH + trow) * IW + j;
        const float4 ta = __ldg(reinterpret_cast<const float4*>(tp));
        const float4 tb = __ldg(reinterpret_cast<const float4*>(tp + 4));
        rT[c][0]=ta.x; rT[c][1]=ta.y; rT[c][2]=ta.z; rT[c][3]=ta.w;
        rT[c][4]=tb.x; rT[c][5]=tb.y; rT[c][6]=tb.z; rT[c][7]=tb.w;
    }
}

__global__ __launch_bounds__(NTHR, 2)
void apply_kernels_k(const float* __restrict__ kern,   // [8][25][508][508]
                     const float* __restrict__ tens,   // [8][3][512][512]
                     float* __restrict__ out)          // weighted ++ kernel_sum
{
    extern __shared__ char smem[];
    const uint32_t sbase = (uint32_t)__cvta_generic_to_shared(smem);

    const int bid = blockIdx.x;
    const int tid = threadIdx.x;

    const uint32_t mb_full0 = sbase + MBAR_OFF;            // full[RING]
    const uint32_t mb_emp0  = sbase + MBAR_OFF + 8 * RING; // empty[RING]

    if (tid == 0) {
        #pragma unroll
        for (int s = 0; s < RING; ++s) {
            mbar_init(mb_full0 + 8u * s, 1);
            mbar_init(mb_emp0  + 8u * s, NCOMP / 32);      // per-warp arrives
        }
    }
    __syncthreads();

    // number of bands this CTA owns
    int nb = 0;
    for (int w = bid; w < NWORK; w += GRIDX) ++nb;
    const int stages_total = nb * GPB;

    if (tid >= NCOMP) {
        // ================= PRODUCER WARP =================
        if ((tid & 31) == 0) {
            const uint64_t pol = policy_evict_first();
            const int pre = (RING < stages_total) ? RING : stages_total;
            for (int s = 0; s < pre; ++s)
                stage_group(kern, sbase, mb_full0, bid, s, pol);
            for (int s = RING; s < stages_total; ++s) {
                const int slot = s % RING;
                const uint32_t par = (uint32_t)(((s - RING) / RING) & 1);
                mbar_wait(mb_emp0 + 8u * slot, par);
                stage_group(kern, sbase, mb_full0, bid, s, pol);
            }
        }
        return;
    }

    // ================= COMPUTE THREADS =================
    const int f  = min(tid, NF4 - 1);     // threads 254/255 duplicate 253
    const int ro = f / (OW / 4);
    const int c4 = f % (OW / 4);
    const int j  = c4 * 4;
    const int lane = tid & 31;

    int s = 0;   // global stage counter
    for (int q = 0, w = bid; w < NWORK; ++q, w += GRIDX) {
        const int band = w % NBAND;
        const int b    = w / NBAND;
        const int irow = band * TH + ro;   // this thread's output row

        float acc[CI][4], ss[4];
        #pragma unroll
        for (int c = 0; c < CI; ++c)
            #pragma unroll
            for (int l = 0; l < 4; ++l) acc[c][l] = 0.f;
        #pragma unroll
        for (int l = 0; l < 4; ++l) ss[l] = 0.f;

        #pragma unroll
        for (int sg = 0; sg < GPB; ++sg, ++s) {
            const int slot = s % RING;
            const uint32_t par = (uint32_t)((s / RING) & 1);
            const int di0 = sg * 2;
            const int nr  = (sg < 2) ? 2 : 1;

            mbar_wait(mb_full0 + 8u * slot, par);
            const char* slotp = smem + slot * SLOTB + ro * (OW * 4) + c4 * 16;

            #pragma unroll
            for (int rr = 0; rr < 2; ++rr) {
                if (rr >= nr) break;
                const int di = di0 + rr;

                // tensor row for this di (L2-resident)
                float rT[CI][8];
                loadT(rT, tens, b, irow + di, j);

                // batch the row's 5 tap-float4s into registers (read slot once)
                float4 k40, k41, k42, k43, k44;
                {
                    const char* rp = slotp + rr * ROWB;
                    k40 = *reinterpret_cast<const float4*>(rp + 0 * TAPB);
                    k41 = *reinterpret_cast<const float4*>(rp + 1 * TAPB);
                    k42 = *reinterpret_cast<const float4*>(rp + 2 * TAPB);
                    k43 = *reinterpret_cast<const float4*>(rp + 3 * TAPB);
                    k44 = *reinterpret_cast<const float4*>(rp + 4 * TAPB);
                }

                // after the LAST row's LDS batch, release the slot BEFORE FMAs
                if (rr == nr - 1) {
                    __syncwarp();
                    if (lane == 0) mbar_arrive(mb_emp0 + 8u * slot);
                }

                const float4 kk[5] = {k40, k41, k42, k43, k44};
                #pragma unroll
                for (int dj = 0; dj < KS; ++dj) {
                    const float kv[4] = {kk[dj].x, kk[dj].y, kk[dj].z, kk[dj].w};
                    #pragma unroll
                    for (int l = 0; l < 4; ++l) {
                        ss[l] += kv[l];
                        #pragma unroll
                        for (int c = 0; c < CI; ++c)
                            acc[c][l] = fmaf(kv[l], rT[c][l + dj], acc[c][l]);
                    }
                }
            }
        }

        // ---- stores for this band (streaming: never re-read) ----
        const size_t pix = (size_t)irow * OW + j;
        #pragma unroll
        for (int c = 0; c < CI; ++c)
            stcs4(&out[((size_t)b * CI + c) * PLANE + pix],
                  make_float4(acc[c][0], acc[c][1], acc[c][2], acc[c][3]));
        stcs4(&out[WTOT + (size_t)b * PLANE + pix],
              make_float4(ss[0], ss[1], ss[2], ss[3]));
    }
}

extern "C" void kernel_launch(void* const* d_in, const int* in_sizes, int n_in,
                              void* d_out, int out_size)
{
    const float* kern = (const float*)d_in[0];   // (8, 25, 508, 508)
    const float* tens = (const float*)d_in[1];   // (8, 3, 512, 512)
    float* out = (float*)d_out;

    cudaFuncSetAttribute(apply_kernels_k,
                         cudaFuncAttributeMaxDynamicSharedMemorySize, SMEM_BYTES);

    dim3 block(NTHR, 1, 1);        // 288 threads: 8 compute warps + 1 producer
    dim3 grid(GRIDX, 1, 1);        // 296 persistent CTAs, uniform 2/SM
    apply_kernels_k<<<grid, block, SMEM_BYTES>>>(kern, tens, out);
}